// round 2
// baseline (speedup 1.0000x reference)
#include <cuda_runtime.h>
#include <math.h>

#define CIN  64
#define COUT 128
#define HH   512
#define WW   512

// Scratch (static __device__ globals — no runtime allocation)
__device__ float  d_y[COUT * HH * WW];     // conv output      (128 MB)
__device__ float2 d_spec[COUT * HH * WW];  // working spectrum (256 MB)

// ---------------------------------------------------------------------------
// Conv 3x3, same padding, cross-correlation (matches lax.conv_general_dilated)
// Block tile: 8 out-channels x 16 h x 64 w. Thread: 8 co x 4 consecutive w px.
// ---------------------------------------------------------------------------
#define CO_T 8
#define HT   16
#define WT   64

__global__ __launch_bounds__(256) void conv3x3_kernel(
    const float* __restrict__ x, const float* __restrict__ wgt,
    const float* __restrict__ bias)
{
    __shared__ float sx[HT + 2][WT + 2];
    __shared__ float sw[CO_T][9];

    const int tid = threadIdx.x;
    const int tx  = tid & 15;    // 16 groups along W, 4 px each
    const int ty  = tid >> 4;    // 16 rows
    const int w0  = blockIdx.x * WT;
    const int h0  = blockIdx.y * HT;
    const int co0 = blockIdx.z * CO_T;

    float acc[CO_T][4];
#pragma unroll
    for (int c = 0; c < CO_T; c++)
#pragma unroll
        for (int p = 0; p < 4; p++) acc[c][p] = 0.f;

    for (int ci = 0; ci < CIN; ci++) {
        // Load padded x tile for this input channel
        for (int i = tid; i < (HT + 2) * (WT + 2); i += 256) {
            int r = i / (WT + 2), c = i % (WT + 2);
            int hh = h0 + r - 1, ww = w0 + c - 1;
            float v = 0.f;
            if (hh >= 0 && hh < HH && ww >= 0 && ww < WW)
                v = x[(ci * HH + hh) * WW + ww];
            sx[r][c] = v;
        }
        if (tid < CO_T * 9) {
            int c = tid / 9, k = tid % 9;
            sw[c][k] = wgt[((co0 + c) * CIN + ci) * 9 + k];
        }
        __syncthreads();

        // Hoist the 3x6 input window into registers
        float xr[3][6];
#pragma unroll
        for (int kh = 0; kh < 3; kh++)
#pragma unroll
            for (int j = 0; j < 6; j++)
                xr[kh][j] = sx[ty + kh][tx * 4 + j];

#pragma unroll
        for (int c = 0; c < CO_T; c++) {
#pragma unroll
            for (int kh = 0; kh < 3; kh++)
#pragma unroll
                for (int kw = 0; kw < 3; kw++) {
                    float wv = sw[c][kh * 3 + kw];
#pragma unroll
                    for (int p = 0; p < 4; p++)
                        acc[c][p] += xr[kh][kw + p] * wv;
                }
        }
        __syncthreads();
    }

#pragma unroll
    for (int c = 0; c < CO_T; c++) {
        float bv = bias[co0 + c];
#pragma unroll
        for (int p = 0; p < 4; p++)
            d_y[((co0 + c) * HH + (h0 + ty)) * WW + (w0 + tx * 4 + p)]
                = acc[c][p] + bv;
    }
}

// ---------------------------------------------------------------------------
// 512-point in-warp radix-2 FFT on shared memory (16 pts/lane).
// Natural-order in/out (bit-reverse permutation then DIT).
// tw[k] = exp(-2*pi*i*k/512) for k in [0,256). inverse => conjugate twiddles.
// ---------------------------------------------------------------------------
__device__ __forceinline__ void build_tw(float2* tw, int tid, int nthr)
{
    for (int i = tid; i < 256; i += nthr) {
        float a = -6.283185307179586f * (float)i / 512.0f;
        float sv, cv;
        __sincosf(a, &sv, &cv);
        // __sincosf is fast-math; refine with one exact pass for accuracy
        sincosf(a, &sv, &cv);
        tw[i] = make_float2(cv, sv);
    }
}

__device__ __forceinline__ void warp_fft512(float2* s, const float2* tw,
                                            int lane, int inv)
{
    // bit-reversal permutation (disjoint swap pairs; one owner per pair)
#pragma unroll
    for (int k = 0; k < 16; k++) {
        int i = lane + 32 * k;
        int j = __brev(i) >> 23;   // 9-bit reversal
        if (j > i) { float2 a = s[i]; s[i] = s[j]; s[j] = a; }
    }
    __syncwarp();

#pragma unroll
    for (int st = 1; st <= 9; st++) {
        const int half  = 1 << (st - 1);
        const int shift = 9 - st;
#pragma unroll
        for (int k = 0; k < 8; k++) {
            int j   = lane + 32 * k;
            int pos = j & (half - 1);
            int i0  = ((j >> (st - 1)) << st) | pos;
            int i1  = i0 + half;
            float2 t = tw[pos << shift];
            float  wi = inv ? -t.y : t.y;
            float2 b = s[i1];
            float tr = b.x * t.x - b.y * wi;
            float ti = b.x * wi + b.y * t.x;
            float2 a = s[i0];
            s[i0] = make_float2(a.x + tr, a.y + ti);
            s[i1] = make_float2(a.x - tr, a.y - ti);
        }
        __syncwarp();
    }
}

// ---------------------------------------------------------------------------
// Pass 1: forward FFT along H (columns). 8 columns per block, warp-per-column.
// ---------------------------------------------------------------------------
__global__ __launch_bounds__(256) void fft_cols_fwd()
{
    __shared__ float2 s[8][516];
    __shared__ float2 tw[256];
    const int tid  = threadIdx.x;
    const int lane = tid & 31;
    const int wp   = tid >> 5;
    const int ch   = blockIdx.y;
    const int w0   = blockIdx.x * 8;

    build_tw(tw, tid, 256);
    for (int i = tid; i < 8 * 512; i += 256) {
        int h = i >> 3, c = i & 7;
        s[c][h] = make_float2(d_y[(ch * HH + h) * WW + w0 + c], 0.f);
    }
    __syncthreads();

    warp_fft512(s[wp], tw, lane, 0);
    __syncthreads();

    for (int i = tid; i < 8 * 512; i += 256) {
        int h = i >> 3, c = i & 7;
        d_spec[(ch * HH + h) * WW + w0 + c] = s[c][h];
    }
}

// ---------------------------------------------------------------------------
// Pass 2: forward FFT along W, mask multiply (with 1/(512*512)), inverse FFT
// along W — fused. Warp-per-row, mask reads fully coalesced.
// ---------------------------------------------------------------------------
__global__ __launch_bounds__(256) void fft_rows_mask(const float* __restrict__ mask)
{
    __shared__ float2 s[8][516];
    __shared__ float2 tw[256];
    const int tid  = threadIdx.x;
    const int lane = tid & 31;
    const int wp   = tid >> 5;
    const int ch   = blockIdx.y;
    const int h    = blockIdx.x * 8 + wp;

    build_tw(tw, tid, 256);
    __syncthreads();   // tw built cooperatively by whole block

    const float2* row = &d_spec[(ch * HH + h) * WW];
#pragma unroll
    for (int k = 0; k < 16; k++)
        s[wp][lane + 32 * k] = row[lane + 32 * k];
    __syncwarp();

    warp_fft512(s[wp], tw, lane, 0);

    const float* mrow = &mask[(ch * HH + h) * WW];
    const float  sc   = 1.0f / (512.0f * 512.0f);
#pragma unroll
    for (int k = 0; k < 16; k++) {
        int idx = lane + 32 * k;
        float m = mrow[idx] * sc;
        float2 v = s[wp][idx];
        s[wp][idx] = make_float2(v.x * m, v.y * m);
    }
    __syncwarp();

    warp_fft512(s[wp], tw, lane, 1);

    float2* orow = &d_spec[(ch * HH + h) * WW];
#pragma unroll
    for (int k = 0; k < 16; k++)
        orow[lane + 32 * k] = s[wp][lane + 32 * k];
}

// ---------------------------------------------------------------------------
// Pass 3: inverse FFT along H (columns), write real part.
// ---------------------------------------------------------------------------
__global__ __launch_bounds__(256) void fft_cols_inv(float* __restrict__ out)
{
    __shared__ float2 s[8][516];
    __shared__ float2 tw[256];
    const int tid  = threadIdx.x;
    const int lane = tid & 31;
    const int wp   = tid >> 5;
    const int ch   = blockIdx.y;
    const int w0   = blockIdx.x * 8;

    build_tw(tw, tid, 256);
    for (int i = tid; i < 8 * 512; i += 256) {
        int h = i >> 3, c = i & 7;
        s[c][h] = d_spec[(ch * HH + h) * WW + w0 + c];
    }
    __syncthreads();

    warp_fft512(s[wp], tw, lane, 1);
    __syncthreads();

    for (int i = tid; i < 8 * 512; i += 256) {
        int h = i >> 3, c = i & 7;
        out[(ch * HH + h) * WW + w0 + c] = s[c][h].x;
    }
}

// ---------------------------------------------------------------------------
extern "C" void kernel_launch(void* const* d_in, const int* in_sizes, int n_in,
                              void* d_out, int out_size)
{
    const float* x    = (const float*)d_in[0];   // (64,512,512)
    const float* wgt  = (const float*)d_in[1];   // (128,64,3,3)
    const float* bias = (const float*)d_in[2];   // (128,)
    const float* mask = (const float*)d_in[3];   // (128,512,512)
    float* out = (float*)d_out;                  // (128,512,512)

    conv3x3_kernel<<<dim3(WW / WT, HH / HT, COUT / CO_T), 256>>>(x, wgt, bias);
    fft_cols_fwd <<<dim3(WW / 8, COUT), 256>>>();
    fft_rows_mask<<<dim3(HH / 8, COUT), 256>>>(mask);
    fft_cols_inv <<<dim3(WW / 8, COUT), 256>>>(out);
}

// round 3
// speedup vs baseline: 1.9091x; 1.9091x over previous
#include <cuda_runtime.h>
#include <math.h>

#define CIN  64
#define COUT 128
#define HH   512
#define WW   512

__device__ float  d_y[COUT * HH * WW];     // conv output      (128 MB)
__device__ float2 d_spec[COUT * HH * WW];  // working spectrum (256 MB)

// ===========================================================================
// Packed fp32x2 helpers (sm_103a dual-FMA path)
// ===========================================================================
__device__ __forceinline__ unsigned long long pack2(float a, float b) {
    unsigned long long r;
    asm("mov.b64 %0, {%1, %2};" : "=l"(r) : "f"(a), "f"(b));
    return r;
}
__device__ __forceinline__ void unpack2(unsigned long long v, float& a, float& b) {
    asm("mov.b64 {%0, %1}, %2;" : "=f"(a), "=f"(b) : "l"(v));
}
__device__ __forceinline__ void fma2(unsigned long long& acc,
                                     unsigned long long x, unsigned long long w) {
    asm("fma.rn.f32x2 %0, %1, %2, %0;" : "+l"(acc) : "l"(x), "l"(w));
}

// ===========================================================================
// Conv 3x3 (cross-correlation, same padding) with packed fp32x2 FMA.
// Block: 8 co x 16 h x 64 w. Thread: 8 co x 4 w px (2 fp32x2 accumulators).
// All weights for the block preloaded once (duplicated pairs, LDS.64 bcast).
// Double-buffered x tile with register prefetch; 1 barrier per ci.
// ===========================================================================
#define CO_T 8
#define HT   16
#define WT   64
#define XPITCH 68   // padded row pitch (floats) -> 16B-aligned rows

__global__ __launch_bounds__(256, 2) void conv3x3_kernel(
    const float* __restrict__ x, const float* __restrict__ wgt,
    const float* __restrict__ bias)
{
    __shared__ unsigned long long swd[CO_T * CIN * 9];      // 36.9 KB
    __shared__ float sx[2][HT + 2][XPITCH];                 // 9.8 KB

    const int tid = threadIdx.x;
    const int tx  = tid & 15;
    const int ty  = tid >> 4;
    const int w0  = blockIdx.x * WT;
    const int h0  = blockIdx.y * HT;
    const int co0 = blockIdx.z * CO_T;

    // ---- one-time weight preload (duplicated into both halves) ----
    for (int i = tid; i < CO_T * CIN * 9; i += 256) {
        int c   = i / (CIN * 9);
        int rem = i - c * (CIN * 9);
        float w = wgt[((co0 + c) * CIN) * 9 + rem];   // ((co0+c)*CIN + ci)*9 + k
        swd[i] = pack2(w, w);
    }

    // ---- initial x tile (ci = 0) ----
    for (int i = tid; i < (HT + 2) * (WT + 2); i += 256) {
        int r = i / (WT + 2), c = i - r * (WT + 2);
        int hh = h0 + r - 1, ww = w0 + c - 1;
        float v = 0.f;
        if (hh >= 0 && hh < HH && ww >= 0 && ww < WW)
            v = x[hh * WW + ww];
        sx[0][r][c] = v;
    }
    __syncthreads();

    unsigned long long acc[CO_T][2];
#pragma unroll
    for (int c = 0; c < CO_T; c++) { acc[c][0] = 0ull; acc[c][1] = 0ull; }

    for (int ci = 0; ci < CIN; ci++) {
        // ---- prefetch next channel tile into registers ----
        float pf[5];
        if (ci + 1 < CIN) {
            const float* xn = x + (ci + 1) * HH * WW;
#pragma unroll
            for (int j = 0; j < 5; j++) {
                int i = tid + 256 * j;
                float v = 0.f;
                if (i < (HT + 2) * (WT + 2)) {
                    int r = i / (WT + 2), c = i - r * (WT + 2);
                    int hh = h0 + r - 1, ww = w0 + c - 1;
                    if (hh >= 0 && hh < HH && ww >= 0 && ww < WW)
                        v = xn[hh * WW + ww];
                }
                pf[j] = v;
            }
        }

        // ---- compute from current buffer ----
        const int b = ci & 1;
        unsigned long long xp[3][5];
#pragma unroll
        for (int kh = 0; kh < 3; kh++) {
            float x0 = sx[b][ty + kh][tx * 4 + 0];
            float x1 = sx[b][ty + kh][tx * 4 + 1];
            float x2 = sx[b][ty + kh][tx * 4 + 2];
            float x3 = sx[b][ty + kh][tx * 4 + 3];
            float x4 = sx[b][ty + kh][tx * 4 + 4];
            float x5 = sx[b][ty + kh][tx * 4 + 5];
            xp[kh][0] = pack2(x0, x1);
            xp[kh][1] = pack2(x1, x2);
            xp[kh][2] = pack2(x2, x3);
            xp[kh][3] = pack2(x3, x4);
            xp[kh][4] = pack2(x4, x5);
        }
        const unsigned long long* wrow = &swd[ci * 9];
#pragma unroll
        for (int c = 0; c < CO_T; c++) {
            const unsigned long long* wc = wrow + c * (CIN * 9);
#pragma unroll
            for (int kh = 0; kh < 3; kh++) {
#pragma unroll
                for (int kw = 0; kw < 3; kw++) {
                    unsigned long long w2 = wc[kh * 3 + kw];
                    fma2(acc[c][0], xp[kh][kw], w2);
                    fma2(acc[c][1], xp[kh][kw + 2], w2);
                }
            }
        }

        // ---- store prefetched tile into other buffer ----
        if (ci + 1 < CIN) {
            const int nb = (ci + 1) & 1;
#pragma unroll
            for (int j = 0; j < 5; j++) {
                int i = tid + 256 * j;
                if (i < (HT + 2) * (WT + 2)) {
                    int r = i / (WT + 2), c = i - r * (WT + 2);
                    sx[nb][r][c] = pf[j];
                }
            }
        }
        __syncthreads();
    }

#pragma unroll
    for (int c = 0; c < CO_T; c++) {
        float bv = bias[co0 + c];
        float p0, p1, p2, p3;
        unpack2(acc[c][0], p0, p1);
        unpack2(acc[c][1], p2, p3);
        float* orow = &d_y[((co0 + c) * HH + (h0 + ty)) * WW + w0 + tx * 4];
        orow[0] = p0 + bv; orow[1] = p1 + bv; orow[2] = p2 + bv; orow[3] = p3 + bv;
    }
}

// ===========================================================================
// Register-resident 512-pt FFT: per-lane FFT-16 (regs) x cross-lane FFT-32
// (shfl). Decomposition n = n1 + 32*n2 (lane n1, reg n2);
// forward output X[k2 + 16*k1] at (lane k1, reg k2). Inverse is the mirror.
// ===========================================================================
template<int INV>
__device__ __forceinline__ void fft16_reg(float2 v[16])
{
    // 4-bit bit-reversal
    float2 t;
    t = v[1];  v[1]  = v[8];  v[8]  = t;
    t = v[2];  v[2]  = v[4];  v[4]  = t;
    t = v[3];  v[3]  = v[12]; v[12] = t;
    t = v[5];  v[5]  = v[10]; v[10] = t;
    t = v[7];  v[7]  = v[14]; v[14] = t;
    t = v[11]; v[11] = v[13]; v[13] = t;

    const float CC[8] = { 1.f,  0.92387953251128674f,  0.70710678118654752f,
                          0.38268343236508977f, 0.f, -0.38268343236508977f,
                         -0.70710678118654752f, -0.92387953251128674f };
    const float SS[8] = { 0.f,  0.38268343236508977f,  0.70710678118654752f,
                          0.92387953251128674f, 1.f,  0.92387953251128674f,
                          0.70710678118654752f,  0.38268343236508977f };
#pragma unroll
    for (int st = 1; st <= 4; st++) {
        const int half = 1 << (st - 1);
#pragma unroll
        for (int j = 0; j < 8; j++) {
            const int pos = j & (half - 1);
            const int i0  = ((j >> (st - 1)) << st) | pos;
            const int i1  = i0 + half;
            const int tj  = pos << (4 - st);
            const float wr = CC[tj];
            const float wi = INV ? SS[tj] : -SS[tj];
            float br = v[i1].x * wr - v[i1].y * wi;
            float bi = v[i1].x * wi + v[i1].y * wr;
            v[i1].x = v[i0].x - br; v[i1].y = v[i0].y - bi;
            v[i0].x += br;          v[i0].y += bi;
        }
    }
}

template<int INV>
__device__ __forceinline__ void fft32_xlane(float2 v[16], int lane)
{
    const unsigned m = 0xffffffffu;
    // 5-bit lane bit-reversal permutation
    int rl = __brev(lane) >> 27;
#pragma unroll
    for (int r = 0; r < 16; r++) {
        v[r].x = __shfl_sync(m, v[r].x, rl);
        v[r].y = __shfl_sync(m, v[r].y, rl);
    }
#pragma unroll
    for (int st = 1; st <= 5; st++) {
        const int half = 1 << (st - 1);
        float ang = (INV ? 3.14159265358979323f : -3.14159265358979323f)
                    * (float)(lane & (half - 1)) / (float)half;
        float wi, wr;
        __sincosf(ang, &wi, &wr);
        const float sgn = (lane & half) ? -1.f : 1.f;
        const bool hi = (lane & half) != 0;
#pragma unroll
        for (int r = 0; r < 16; r++) {
            float px = __shfl_xor_sync(m, v[r].x, half);
            float py = __shfl_xor_sync(m, v[r].y, half);
            float bx = hi ? v[r].x : px;
            float by = hi ? v[r].y : py;
            float ax = hi ? px : v[r].x;
            float ay = hi ? py : v[r].y;
            float tx = bx * wr - by * wi;
            float ty = bx * wi + by * wr;
            v[r].x = fmaf(sgn, tx, ax);
            v[r].y = fmaf(sgn, ty, ay);
        }
    }
}

template<int INV>
__device__ __forceinline__ void twiddle512(float2 v[16], int lane)
{
    float ang = (INV ? 6.28318530717958648f : -6.28318530717958648f)
                * (float)lane / 512.f;
    float s, c;
    __sincosf(ang, &s, &c);
    float wr = 1.f, wi = 0.f;
#pragma unroll
    for (int r = 1; r < 16; r++) {
        float nwr = wr * c - wi * s;
        float nwi = wr * s + wi * c;
        wr = nwr; wi = nwi;
        float xr = v[r].x, xi = v[r].y;
        v[r].x = xr * wr - xi * wi;
        v[r].y = xr * wi + xi * wr;
    }
}

__device__ __forceinline__ void fft512_fwd(float2 v[16], int lane)
{   // in: (lane n1, reg n2), n = n1+32*n2  -> out: (lane k1, reg k2), k = k2+16*k1
    fft16_reg<0>(v);
    twiddle512<0>(v, lane);
    fft32_xlane<0>(v, lane);
}
__device__ __forceinline__ void fft512_inv(float2 v[16], int lane)
{   // in: (lane k1, reg k2), k = k2+16*k1  -> out: (lane n1, reg n2), n = n1+32*n2
    fft32_xlane<1>(v, lane);
    twiddle512<1>(v, lane);
    fft16_reg<1>(v);
}

// XOR swizzle for the k-major float2 slab (logical idx = 8*k + c, k<512, c<8)
__device__ __forceinline__ int swz(int idx) { return idx ^ ((idx >> 7) & 15); }

// ===========================================================================
// Pass 1: forward FFT along H. 8 columns/block, warp-per-column.
// ===========================================================================
__global__ __launch_bounds__(256) void fft_cols_fwd()
{
    __shared__ char raw[32768];
    float*  sIn  = (float*)raw;     // [h*9 + c], 18.4 KB
    float2* sOut = (float2*)raw;    // swizzled [8k+c], 32 KB

    const int tid  = threadIdx.x;
    const int lane = tid & 31;
    const int wp   = tid >> 5;
    const int ch   = blockIdx.y;
    const int w0   = blockIdx.x * 8;

    for (int i = tid; i < 4096; i += 256) {
        int h = i >> 3, c = i & 7;
        sIn[h * 9 + c] = d_y[(ch * HH + h) * WW + w0 + c];
    }
    __syncthreads();

    float2 v[16];
#pragma unroll
    for (int r = 0; r < 16; r++)
        v[r] = make_float2(sIn[(lane + 32 * r) * 9 + wp], 0.f);
    __syncthreads();   // all reads of sIn done before sOut overwrites

    fft512_fwd(v, lane);

#pragma unroll
    for (int r = 0; r < 16; r++) {
        int k = r + 16 * lane;
        sOut[swz((k << 3) | wp)] = v[r];
    }
    __syncthreads();

    for (int i = tid; i < 4096; i += 256) {
        int k = i >> 3, c = i & 7;
        d_spec[(ch * HH + k) * WW + w0 + c] = sOut[swz(i)];
    }
}

// ===========================================================================
// Pass 2: fused forward FFT along W, mask*(1/N^2), inverse FFT along W.
// Warp-per-row; data stays in registers; mask staged via padded smem.
// ===========================================================================
__global__ __launch_bounds__(256) void fft_rows_mask(const float* __restrict__ mask)
{
    __shared__ float sm[8][528];   // 512 + 16 pad  (idx i -> i + (i>>5))

    const int tid  = threadIdx.x;
    const int lane = tid & 31;
    const int wp   = tid >> 5;
    const int ch   = blockIdx.y;
    const int h    = blockIdx.x * 8 + wp;

    float2* row  = &d_spec[(ch * HH + h) * WW];
    const float* mrow = &mask[(ch * HH + h) * WW];

    float2 v[16];
#pragma unroll
    for (int r = 0; r < 16; r++)
        v[r] = row[lane + 32 * r];             // coalesced 256B per load
#pragma unroll
    for (int t = 0; t < 16; t++) {
        int i = lane + 32 * t;
        sm[wp][i + (i >> 5)] = mrow[i];        // coalesced mask stage
    }

    fft512_fwd(v, lane);
    __syncwarp();

    const float sc = 1.0f / (512.0f * 512.0f);
#pragma unroll
    for (int r = 0; r < 16; r++) {
        int k = r + 16 * lane;                 // natural frequency index
        float mv = sm[wp][k + (k >> 5)] * sc;
        v[r].x *= mv; v[r].y *= mv;
    }

    fft512_inv(v, lane);

#pragma unroll
    for (int r = 0; r < 16; r++)
        row[lane + 32 * r] = v[r];             // coalesced
}

// ===========================================================================
// Pass 3: inverse FFT along H, write real part.
// ===========================================================================
__global__ __launch_bounds__(256) void fft_cols_inv(float* __restrict__ out)
{
    __shared__ char raw[32768];
    float2* sIn  = (float2*)raw;    // swizzled [8k+c]
    float*  sOut = (float*)raw;     // [h*9 + c]

    const int tid  = threadIdx.x;
    const int lane = tid & 31;
    const int wp   = tid >> 5;
    const int ch   = blockIdx.y;
    const int w0   = blockIdx.x * 8;

    for (int i = tid; i < 4096; i += 256) {
        int k = i >> 3, c = i & 7;
        sIn[swz(i)] = d_spec[(ch * HH + k) * WW + w0 + c];
    }
    __syncthreads();

    float2 v[16];
#pragma unroll
    for (int r = 0; r < 16; r++) {
        int k = r + 16 * lane;
        v[r] = sIn[swz((k << 3) | wp)];
    }
    __syncthreads();   // all reads done before float overwrite

    fft512_inv(v, lane);

#pragma unroll
    for (int r = 0; r < 16; r++)
        sOut[(lane + 32 * r) * 9 + wp] = v[r].x;
    __syncthreads();

    for (int i = tid; i < 4096; i += 256) {
        int hh = i >> 3, c = i & 7;
        out[(ch * HH + hh) * WW + w0 + c] = sOut[hh * 9 + c];
    }
}

// ===========================================================================
extern "C" void kernel_launch(void* const* d_in, const int* in_sizes, int n_in,
                              void* d_out, int out_size)
{
    const float* x    = (const float*)d_in[0];   // (64,512,512)
    const float* wgt  = (const float*)d_in[1];   // (128,64,3,3)
    const float* bias = (const float*)d_in[2];   // (128,)
    const float* mask = (const float*)d_in[3];   // (128,512,512)
    float* out = (float*)d_out;                  // (128,512,512)

    conv3x3_kernel<<<dim3(WW / WT, HH / HT, COUT / CO_T), 256>>>(x, wgt, bias);
    fft_cols_fwd <<<dim3(WW / 8, COUT), 256>>>();
    fft_rows_mask<<<dim3(HH / 8, COUT), 256>>>(mask);
    fft_cols_inv <<<dim3(WW / 8, COUT), 256>>>(out);
}